// round 11
// baseline (speedup 1.0000x reference)
#include <cuda_runtime.h>
#include <cuda_bf16.h>
#include <cstdint>

#define NTHR 256
#define TMR  32

// Weight blob: per layer 64 k8-chunks x [hl][n-tile][lane] -> 262144 words (1MB).
// word(l, k8t, hl, n, cp) at  l*262144 + (k8t*2+hl)*2048 + (n>>3)*32 + (n&7)*4 + cp
// holds bf16 pair (k = 8*k8t + 2cp, +1) of column n. B-fragment load = wb[nt*32 + lane].
__device__ __align__(16) uint32_t gW[6u * 262144u];   // 6 MB

// ---- smem byte offsets ----
#define SM_ACT_HI 0         // 8192 words
#define SM_ACT_LO 32768     // 8192 words
#define SM_WBUF   65536     // 2 x up to 4096 words (32 KB)
#define SM_BIAS   98304     // 512 f
#define SM_LW     100352    // 512 f
#define SM_LB     102400    // 512 f
#define SM_WOUT   104448    // 3*512 f
#define SM_RED    110592    // 4*32*2 f = 1024 B
#define SM_TOTAL  111616
// overlays inside WBUF (used only when weight buffer is dead):
#define SM_XIN    SM_WBUF   // layer0 input staging (768 B)
#define SM_OUTACC SM_WBUF   // LAST epilogue partials (1536 B)

__device__ __forceinline__ void cp16(void* dst, const void* src) {
    unsigned s = (unsigned)__cvta_generic_to_shared(dst);
    asm volatile("cp.async.cg.shared.global [%0], [%1], 16;" :: "r"(s), "l"(src));
}
__device__ __forceinline__ void cp_commit() { asm volatile("cp.async.commit_group;"); }
__device__ __forceinline__ void cp_wait0()  { asm volatile("cp.async.wait_group 0;"); }

__device__ __forceinline__ void mma_k8(float* d, uint32_t a0, uint32_t a1, uint32_t b0) {
    asm volatile("mma.sync.aligned.m16n8k8.row.col.f32.bf16.bf16.f32 "
        "{%0,%1,%2,%3}, {%4,%5}, {%6}, {%0,%1,%2,%3};"
        : "+f"(d[0]), "+f"(d[1]), "+f"(d[2]), "+f"(d[3])
        : "r"(a0), "r"(a1), "r"(b0));
}

__device__ __forceinline__ uint32_t pack_split(float a, float b, uint32_t& lo) {
    __nv_bfloat16 ha = __float2bfloat16(a), hb = __float2bfloat16(b);
    __nv_bfloat16 la = __float2bfloat16(a - __bfloat162float(ha));
    __nv_bfloat16 lb = __float2bfloat16(b - __bfloat162float(hb));
    lo = (uint32_t)__bfloat16_as_ushort(la) | ((uint32_t)__bfloat16_as_ushort(lb) << 16);
    return (uint32_t)__bfloat16_as_ushort(ha) | ((uint32_t)__bfloat16_as_ushort(hb) << 16);
}

template<int F>
__host__ __device__ constexpr int hdim(int l) {
    return (F == 0) ? 256 : ((F == 2) ? 512 : ((l % 2 == 0) ? 512 : 256));
}

// ---------------- prep: split fp32 weights into hi/lo bf16 blob ----------------
__global__ void split_weights(const float* __restrict__ Ws) {
    int id = blockIdx.x * 256 + threadIdx.x;        // 6*512*256 k-pairs
    int l  = id / (512 * 256);
    int r  = id - l * (512 * 256);
    int n  = r >> 8;
    int kp = r & 255;
    const float* W = Ws + ((size_t)l * 512 + n) * 512;
    float w0 = W[2 * kp], w1 = W[2 * kp + 1];
    __nv_bfloat16 h0 = __float2bfloat16(w0), h1 = __float2bfloat16(w1);
    __nv_bfloat16 l0 = __float2bfloat16(w0 - __bfloat162float(h0));
    __nv_bfloat16 l1 = __float2bfloat16(w1 - __bfloat162float(h1));
    int k8t = kp >> 2, cp = kp & 3;
    uint32_t base = (uint32_t)l * 262144u + (uint32_t)(k8t * 2) * 2048u
                  + (uint32_t)((n >> 3) * 32 + (n & 7) * 4 + cp);
    gW[base]        = (uint32_t)__bfloat16_as_ushort(h0) | ((uint32_t)__bfloat16_as_ushort(h1) << 16);
    gW[base + 2048] = (uint32_t)__bfloat16_as_ushort(l0) | ((uint32_t)__bfloat16_as_ushort(l1) << 16);
}

// ---------------- layer 0 (K = 6) ----------------
template<int HOUT>
__device__ __noinline__ void layer0(uint8_t* sm,
    const float* __restrict__ inputs, const float* __restrict__ W_in,
    const float* __restrict__ b_in, const float* __restrict__ lnw,
    const float* __restrict__ lnb, int rowbase)
{
    uint32_t* actHi = (uint32_t*)(sm + SM_ACT_HI);
    uint32_t* actLo = (uint32_t*)(sm + SM_ACT_LO);
    float* sW    = (float*)(sm + SM_WBUF + 4096);   // after xin, inside dead wbuf
    float* sBias = (float*)(sm + SM_BIAS);
    float* sLw   = (float*)(sm + SM_LW);
    float* sLb   = (float*)(sm + SM_LB);
    float* xin   = (float*)(sm + SM_XIN);
    const int tid = threadIdx.x;

    for (int i = tid; i < HOUT * 6; i += NTHR) sW[i] = W_in[i];
    for (int i = tid; i < HOUT; i += NTHR) { sBias[i] = b_in[i]; sLw[i] = lnw[i]; sLb[i] = lnb[i]; }
    for (int i = tid; i < TMR * 6; i += NTHR) xin[i] = inputs[rowbase * 6 + i];
    __syncthreads();

    const int row = tid >> 3, sub = (tid >> 2) & 1, cp = tid & 3;
    float x[6];
    #pragma unroll
    for (int k = 0; k < 6; ++k) x[k] = xin[row * 6 + k];

    float s = 0.f, q = 0.f;
    for (int nt = sub; nt < HOUT / 8; nt += 2) {
        #pragma unroll
        for (int e = 0; e < 2; ++e) {
            int col = 8 * nt + 2 * cp + e;
            const float* w = sW + col * 6;
            float v = sBias[col];
            #pragma unroll
            for (int k = 0; k < 6; ++k) v += x[k] * w[k];
            s += v; q += v * v;
        }
    }
    #pragma unroll
    for (int o = 1; o <= 4; o <<= 1) {
        s += __shfl_xor_sync(0xffffffffu, s, o);
        q += __shfl_xor_sync(0xffffffffu, q, o);
    }
    const float mean = s * (1.0f / HOUT);
    const float rstd = rsqrtf(q * (1.0f / HOUT) - mean * mean + 1e-5f);

    for (int nt = sub; nt < HOUT / 8; nt += 2) {
        float y[2];
        #pragma unroll
        for (int e = 0; e < 2; ++e) {
            int col = 8 * nt + 2 * cp + e;
            const float* w = sW + col * 6;
            float v = sBias[col];
            #pragma unroll
            for (int k = 0; k < 6; ++k) v += x[k] * w[k];
            y[e] = fmaxf((v - mean) * rstd * sLw[col] + sLb[col], 0.f);
        }
        uint32_t lo;
        uint32_t hi = pack_split(y[0], y[1], lo);
        uint32_t idx = (uint32_t)(nt * TMR + row) * 4u + (uint32_t)cp;
        actHi[idx] = hi; actLo[idx] = lo;
    }
    __syncthreads();
}

// ---------------- mid layer: k8 HMMA 3-split GEMM + LN + ReLU (+ fused out) ----
template<int HIN, int HOUT, bool LAST>
__device__ __noinline__ void mid_layer(uint8_t* sm, int lane, int mb, int nq,
    int lidx, int fidx,
    const float* __restrict__ bias, const float* __restrict__ lnw,
    const float* __restrict__ lnb, const float* __restrict__ W_out,
    const float* __restrict__ b_out, float* __restrict__ out, int rowbase)
{
    constexpr int KT = HIN / 8;         // k8 chunks
    constexpr int NT = HOUT / 32;       // n8 tiles per warp (warp covers HOUT/4 cols)
    constexpr int CW = HOUT * 8;        // chunk words (2 planes x HOUT*4)
    constexpr int NC4 = CW / 4 / NTHR;  // uint4 copies per thread per chunk

    uint32_t* actHi = (uint32_t*)(sm + SM_ACT_HI);
    uint32_t* actLo = (uint32_t*)(sm + SM_ACT_LO);
    uint32_t* wbuf  = (uint32_t*)(sm + SM_WBUF);
    float* sBias  = (float*)(sm + SM_BIAS);
    float* sLw    = (float*)(sm + SM_LW);
    float* sLb    = (float*)(sm + SM_LB);
    float* sWout  = (float*)(sm + SM_WOUT);
    float* red    = (float*)(sm + SM_RED);
    float* outAcc = (float*)(sm + SM_OUTACC);
    const int tid = threadIdx.x;

    for (int i = tid; i < HOUT; i += NTHR) { sBias[i] = bias[i]; sLw[i] = lnw[i]; sLb[i] = lnb[i]; }
    if (LAST)
        for (int i = tid; i < 3 * HOUT; i += NTHR)
            sWout[i] = W_out[(i / HOUT) * 512 + (i % HOUT)];

    const uint32_t* wsrc = gW + (uint32_t)lidx * 262144u;
    auto stage = [&](int kt, int p) {
        const uint32_t* src = wsrc + (uint32_t)(kt * 2) * 2048u;
        uint32_t* dst = wbuf + p * CW;
        #pragma unroll
        for (int t = 0; t < NC4; ++t) {
            int u = (tid + t * NTHR) * 4;            // word within chunk
            int hl = u / (HOUT * 4);
            int rem = u - hl * (HOUT * 4);
            cp16(dst + u, src + hl * 2048 + rem);
        }
    };

    float acc[NT][4];
    #pragma unroll
    for (int t = 0; t < NT; ++t) { acc[t][0] = acc[t][1] = acc[t][2] = acc[t][3] = 0.f; }

    const int row0 = mb * 16 + (lane >> 2);
    const int cp   = lane & 3;
    const int ntg0 = nq * NT;

    stage(0, 0); cp_commit();
    for (int kt = 0; kt < KT; ++kt) {
        cp_wait0();
        __syncthreads();
        if (kt + 1 < KT) { stage(kt + 1, (kt + 1) & 1); cp_commit(); }

        const uint32_t* wb = wbuf + (kt & 1) * CW;
        uint32_t ia = (uint32_t)(kt * TMR + row0) * 4u + cp;
        uint32_t ah0 = actHi[ia], ah1 = actHi[ia + 32];
        uint32_t al0 = actLo[ia], al1 = actLo[ia + 32];

        #pragma unroll
        for (int t = 0; t < NT; ++t) {
            const uint32_t* bp = wb + (uint32_t)(ntg0 + t) * 32u + lane;
            uint32_t bh = bp[0];
            uint32_t bl = bp[HOUT * 4];
            mma_k8(acc[t], ah0, ah1, bh);
            mma_k8(acc[t], al0, al1, bh);
            mma_k8(acc[t], ah0, ah1, bl);
        }
    }

    // ---- epilogue ----
    float s0 = 0.f, q0 = 0.f, s1 = 0.f, q1 = 0.f;
    #pragma unroll
    for (int t = 0; t < NT; ++t) {
        float2 bv = *(const float2*)(sBias + 8 * (ntg0 + t) + 2 * cp);
        acc[t][0] += bv.x; acc[t][1] += bv.y; acc[t][2] += bv.x; acc[t][3] += bv.y;
        s0 += acc[t][0] + acc[t][1]; q0 += acc[t][0] * acc[t][0] + acc[t][1] * acc[t][1];
        s1 += acc[t][2] + acc[t][3]; q1 += acc[t][2] * acc[t][2] + acc[t][3] * acc[t][3];
    }
    #pragma unroll
    for (int o = 1; o <= 2; o <<= 1) {
        s0 += __shfl_xor_sync(0xffffffffu, s0, o); q0 += __shfl_xor_sync(0xffffffffu, q0, o);
        s1 += __shfl_xor_sync(0xffffffffu, s1, o); q1 += __shfl_xor_sync(0xffffffffu, q1, o);
    }
    if (cp == 0) {
        red[(nq * 32 + row0) * 2 + 0] = s0;      red[(nq * 32 + row0) * 2 + 1] = q0;
        red[(nq * 32 + row0 + 8) * 2 + 0] = s1;  red[(nq * 32 + row0 + 8) * 2 + 1] = q1;
    }
    __syncthreads();
    float S0 = 0.f, Q0 = 0.f, S1 = 0.f, Q1 = 0.f;
    #pragma unroll
    for (int g = 0; g < 4; ++g) {
        S0 += red[(g * 32 + row0) * 2 + 0];     Q0 += red[(g * 32 + row0) * 2 + 1];
        S1 += red[(g * 32 + row0 + 8) * 2 + 0]; Q1 += red[(g * 32 + row0 + 8) * 2 + 1];
    }
    const float mean0 = S0 * (1.0f / HOUT);
    const float rstd0 = rsqrtf(Q0 * (1.0f / HOUT) - mean0 * mean0 + 1e-5f);
    const float mean1 = S1 * (1.0f / HOUT);
    const float rstd1 = rsqrtf(Q1 * (1.0f / HOUT) - mean1 * mean1 + 1e-5f);

    if (!LAST) {
        #pragma unroll
        for (int t = 0; t < NT; ++t) {
            int col0 = 8 * (ntg0 + t) + 2 * cp;
            float2 lwv = *(const float2*)(sLw + col0);
            float2 lbv = *(const float2*)(sLb + col0);
            float y00 = fmaxf((acc[t][0] - mean0) * rstd0 * lwv.x + lbv.x, 0.f);
            float y01 = fmaxf((acc[t][1] - mean0) * rstd0 * lwv.y + lbv.y, 0.f);
            float y10 = fmaxf((acc[t][2] - mean1) * rstd1 * lwv.x + lbv.x, 0.f);
            float y11 = fmaxf((acc[t][3] - mean1) * rstd1 * lwv.y + lbv.y, 0.f);
            uint32_t lo0, lo1;
            uint32_t hi0 = pack_split(y00, y01, lo0);
            uint32_t hi1 = pack_split(y10, y11, lo1);
            uint32_t idx0 = (uint32_t)((ntg0 + t) * TMR + row0) * 4u + cp;
            actHi[idx0] = hi0;      actLo[idx0] = lo0;
            actHi[idx0 + 32] = hi1; actLo[idx0 + 32] = lo1;
        }
        __syncthreads();
    } else {
        float p0[3] = {0.f, 0.f, 0.f}, p1[3] = {0.f, 0.f, 0.f};
        #pragma unroll
        for (int t = 0; t < NT; ++t) {
            int col0 = 8 * (ntg0 + t) + 2 * cp;
            float2 lwv = *(const float2*)(sLw + col0);
            float2 lbv = *(const float2*)(sLb + col0);
            float y00 = fmaxf((acc[t][0] - mean0) * rstd0 * lwv.x + lbv.x, 0.f);
            float y01 = fmaxf((acc[t][1] - mean0) * rstd0 * lwv.y + lbv.y, 0.f);
            float y10 = fmaxf((acc[t][2] - mean1) * rstd1 * lwv.x + lbv.x, 0.f);
            float y11 = fmaxf((acc[t][3] - mean1) * rstd1 * lwv.y + lbv.y, 0.f);
            #pragma unroll
            for (int o = 0; o < 3; ++o) {
                float w0 = sWout[o * HOUT + col0], w1 = sWout[o * HOUT + col0 + 1];
                p0[o] += y00 * w0 + y01 * w1;
                p1[o] += y10 * w0 + y11 * w1;
            }
        }
        #pragma unroll
        for (int o = 0; o < 3; ++o) {
            #pragma unroll
            for (int m = 1; m <= 2; m <<= 1) {
                p0[o] += __shfl_xor_sync(0xffffffffu, p0[o], m);
                p1[o] += __shfl_xor_sync(0xffffffffu, p1[o], m);
            }
        }
        __syncthreads();   // all MMAs/B-reads done before outAcc overlays wbuf
        if (cp == 0) {
            #pragma unroll
            for (int o = 0; o < 3; ++o) {
                outAcc[(nq * 32 + row0) * 3 + o] = p0[o];
                outAcc[(nq * 32 + row0 + 8) * 3 + o] = p1[o];
            }
        }
        __syncthreads();
        if (tid < 96) {
            int row = tid / 3, o = tid - row * 3;
            float v = b_out[o];
            #pragma unroll
            for (int g = 0; g < 4; ++g) v += outAcc[(g * 32 + row) * 3 + o];
            out[(size_t)(rowbase + row) * 9 + fidx * 3 + o] = v;
        }
    }
}

// ---------------- fused kernel per factor ----------------
template<int F>
__global__ void __launch_bounds__(NTHR, 2) mipnet_tc(
    const float* __restrict__ inputs,
    const float* __restrict__ W_in, const float* __restrict__ b_in,
    const float* __restrict__ bs,
    const float* __restrict__ ln_w, const float* __restrict__ ln_b,
    const float* __restrict__ W_out, const float* __restrict__ b_out,
    float* __restrict__ out)
{
    extern __shared__ uint8_t sm[];
    const int tid  = threadIdx.x;
    const int lane = tid & 31;
    const int wid  = tid >> 5;
    const int mb   = wid & 1;     // 16-row block
    const int nq   = wid >> 1;    // column quarter
    const int rowbase = blockIdx.x * TMR;

    layer0<hdim<F>(0)>(sm, inputs, W_in, b_in, ln_w, ln_b, rowbase);
    mid_layer<hdim<F>(0), hdim<F>(1), false>(sm, lane, mb, nq, 0, F, bs,
        ln_w + 512,  ln_b + 512,  W_out, b_out, out, rowbase);
    mid_layer<hdim<F>(1), hdim<F>(2), false>(sm, lane, mb, nq, 1, F, bs + 512,
        ln_w + 1024, ln_b + 1024, W_out, b_out, out, rowbase);
    mid_layer<hdim<F>(2), hdim<F>(3), false>(sm, lane, mb, nq, 2, F, bs + 1024,
        ln_w + 1536, ln_b + 1536, W_out, b_out, out, rowbase);
    mid_layer<hdim<F>(3), hdim<F>(4), false>(sm, lane, mb, nq, 3, F, bs + 1536,
        ln_w + 2048, ln_b + 2048, W_out, b_out, out, rowbase);
    mid_layer<hdim<F>(4), hdim<F>(5), false>(sm, lane, mb, nq, 4, F, bs + 2048,
        ln_w + 2560, ln_b + 2560, W_out, b_out, out, rowbase);
    mid_layer<hdim<F>(5), hdim<F>(6), true >(sm, lane, mb, nq, 5, F, bs + 2560,
        ln_w + 3072, ln_b + 3072, W_out, b_out, out, rowbase);
}

extern "C" void kernel_launch(void* const* d_in, const int* in_sizes, int n_in,
                              void* d_out, int out_size) {
    const float* inputs = (const float*)d_in[0];
    const float* W_in   = (const float*)d_in[1];
    const float* b_in   = (const float*)d_in[2];
    const float* Ws     = (const float*)d_in[3];
    const float* bs     = (const float*)d_in[4];
    const float* ln_w   = (const float*)d_in[5];
    const float* ln_b   = (const float*)d_in[6];
    const float* W_out  = (const float*)d_in[7];
    const float* b_out  = (const float*)d_in[8];
    float* out = (float*)d_out;

    const int Nrows = in_sizes[0] / 6;
    const int tiles = Nrows / TMR;      // 4096

    cudaFuncSetAttribute(mipnet_tc<0>, cudaFuncAttributeMaxDynamicSharedMemorySize, SM_TOTAL);
    cudaFuncSetAttribute(mipnet_tc<1>, cudaFuncAttributeMaxDynamicSharedMemorySize, SM_TOTAL);
    cudaFuncSetAttribute(mipnet_tc<2>, cudaFuncAttributeMaxDynamicSharedMemorySize, SM_TOTAL);

    split_weights<<<3072, 256>>>(Ws);

    mipnet_tc<0><<<tiles, NTHR, SM_TOTAL>>>(inputs, W_in, b_in, bs, ln_w, ln_b, W_out, b_out, out);
    mipnet_tc<1><<<tiles, NTHR, SM_TOTAL>>>(inputs, W_in, b_in, bs, ln_w, ln_b, W_out, b_out, out);
    mipnet_tc<2><<<tiles, NTHR, SM_TOTAL>>>(inputs, W_in, b_in, bs, ln_w, ln_b, W_out, b_out, out);
}

// round 12
// speedup vs baseline: 1.4087x; 1.4087x over previous
#include <cuda_runtime.h>
#include <cuda_bf16.h>
#include <cstdint>

#define NTHR 256
#define TMR  32

// Weight blob (k16 layout, proven in R10): per layer 32 k16-chunks x [hl][n-tile][pos].
// word(l, kt, hl, n, pos) at (l*32+kt)*8192 + hl*4096 + n*8 + pos,
// pos = 2*(kpl&3) + (kpl>>2) for k-pair kpl (0..7), so the B-fragment pair
// (kpl, kpl+4) is one contiguous 8B load: uint2 at  nt*64 + (lane>>2)*8 + 2*(lane&3).
__device__ __align__(16) uint32_t gW[6u * 262144u];   // 6 MB

// ---- smem byte offsets ----
#define SM_ACT_HI 0         // 8192 words (32 rows x 512 cols bf16-pairs)
#define SM_ACT_LO 32768     // 8192 words
#define SM_WBUF   65536     // 32 KB: 2 x 16KB (HOUT=256, DB) or 1 x 32KB (HOUT=512)
#define SM_BIAS   98304     // 512 f
#define SM_LW     100352    // 512 f
#define SM_LB     102400    // 512 f
#define SM_WOUT   104448    // 3*512 f
#define SM_RED    110592    // 4*32*2 f
#define SM_TOTAL  111616
// overlays inside WBUF (only when weight buffer is dead):
#define SM_XIN    SM_WBUF   // layer0 input staging
#define SM_OUTACC SM_WBUF   // LAST epilogue partials

__device__ __forceinline__ void cp16(void* dst, const void* src) {
    unsigned s = (unsigned)__cvta_generic_to_shared(dst);
    asm volatile("cp.async.cg.shared.global [%0], [%1], 16;" :: "r"(s), "l"(src));
}
__device__ __forceinline__ void cp_commit() { asm volatile("cp.async.commit_group;"); }
__device__ __forceinline__ void cp_wait0()  { asm volatile("cp.async.wait_group 0;"); }

__device__ __forceinline__ void mma_k16(float* d,
                                        uint32_t a0, uint32_t a1, uint32_t a2, uint32_t a3,
                                        uint32_t b0, uint32_t b1) {
    asm volatile("mma.sync.aligned.m16n8k16.row.col.f32.bf16.bf16.f32 "
        "{%0,%1,%2,%3}, {%4,%5,%6,%7}, {%8,%9}, {%0,%1,%2,%3};"
        : "+f"(d[0]), "+f"(d[1]), "+f"(d[2]), "+f"(d[3])
        : "r"(a0), "r"(a1), "r"(a2), "r"(a3), "r"(b0), "r"(b1));
}

__device__ __forceinline__ uint32_t pack_split(float a, float b, uint32_t& lo) {
    __nv_bfloat16 ha = __float2bfloat16(a), hb = __float2bfloat16(b);
    __nv_bfloat16 la = __float2bfloat16(a - __bfloat162float(ha));
    __nv_bfloat16 lb = __float2bfloat16(b - __bfloat162float(hb));
    lo = (uint32_t)__bfloat16_as_ushort(la) | ((uint32_t)__bfloat16_as_ushort(lb) << 16);
    return (uint32_t)__bfloat16_as_ushort(ha) | ((uint32_t)__bfloat16_as_ushort(hb) << 16);
}

template<int F>
__host__ __device__ constexpr int hdim(int l) {
    return (F == 0) ? 256 : ((F == 2) ? 512 : ((l % 2 == 0) ? 512 : 256));
}

// ---------------- prep: split fp32 weights into hi/lo bf16 blob (k16 layout) ----
__global__ void split_weights(const float* __restrict__ Ws) {
    int id = blockIdx.x * 256 + threadIdx.x;        // 6*512*256 k-pairs
    int l  = id / (512 * 256);
    int r  = id - l * (512 * 256);
    int n  = r >> 8;
    int kp = r & 255;
    const float* W = Ws + ((size_t)l * 512 + n) * 512;
    float w0 = W[2 * kp], w1 = W[2 * kp + 1];
    __nv_bfloat16 h0 = __float2bfloat16(w0), h1 = __float2bfloat16(w1);
    __nv_bfloat16 l0 = __float2bfloat16(w0 - __bfloat162float(h0));
    __nv_bfloat16 l1 = __float2bfloat16(w1 - __bfloat162float(h1));
    int kt = kp >> 3, kpl = kp & 7;
    int pos = 2 * (kpl & 3) + (kpl >> 2);
    uint32_t base = (uint32_t)((l * 32 + kt) * 2) * 4096u + (uint32_t)(n * 8 + pos);
    gW[base]        = (uint32_t)__bfloat16_as_ushort(h0) | ((uint32_t)__bfloat16_as_ushort(h1) << 16);
    gW[base + 4096] = (uint32_t)__bfloat16_as_ushort(l0) | ((uint32_t)__bfloat16_as_ushort(l1) << 16);
}

// ---------------- layer 0 (K = 6) ----------------
template<int HOUT>
__device__ __noinline__ void layer0(uint8_t* sm,
    const float* __restrict__ inputs, const float* __restrict__ W_in,
    const float* __restrict__ b_in, const float* __restrict__ lnw,
    const float* __restrict__ lnb, int rowbase)
{
    uint32_t* actHi = (uint32_t*)(sm + SM_ACT_HI);
    uint32_t* actLo = (uint32_t*)(sm + SM_ACT_LO);
    float* sW    = (float*)(sm + SM_WBUF + 4096);   // after xin, inside dead wbuf
    float* sBias = (float*)(sm + SM_BIAS);
    float* sLw   = (float*)(sm + SM_LW);
    float* sLb   = (float*)(sm + SM_LB);
    float* xin   = (float*)(sm + SM_XIN);
    const int tid = threadIdx.x;

    for (int i = tid; i < HOUT * 6; i += NTHR) sW[i] = W_in[i];
    for (int i = tid; i < HOUT; i += NTHR) { sBias[i] = b_in[i]; sLw[i] = lnw[i]; sLb[i] = lnb[i]; }
    for (int i = tid; i < TMR * 6; i += NTHR) xin[i] = inputs[rowbase * 6 + i];
    __syncthreads();

    const int row = tid >> 3, sub = (tid >> 2) & 1, cp = tid & 3;
    float x[6];
    #pragma unroll
    for (int k = 0; k < 6; ++k) x[k] = xin[row * 6 + k];

    float s = 0.f, q = 0.f;
    for (int nt = sub; nt < HOUT / 8; nt += 2) {
        #pragma unroll
        for (int e = 0; e < 2; ++e) {
            int col = 8 * nt + 2 * cp + e;
            const float* w = sW + col * 6;
            float v = sBias[col];
            #pragma unroll
            for (int k = 0; k < 6; ++k) v += x[k] * w[k];
            s += v; q += v * v;
        }
    }
    #pragma unroll
    for (int o = 1; o <= 4; o <<= 1) {
        s += __shfl_xor_sync(0xffffffffu, s, o);
        q += __shfl_xor_sync(0xffffffffu, q, o);
    }
    const float mean = s * (1.0f / HOUT);
    const float rstd = rsqrtf(q * (1.0f / HOUT) - mean * mean + 1e-5f);

    for (int nt = sub; nt < HOUT / 8; nt += 2) {
        float y[2];
        #pragma unroll
        for (int e = 0; e < 2; ++e) {
            int col = 8 * nt + 2 * cp + e;
            const float* w = sW + col * 6;
            float v = sBias[col];
            #pragma unroll
            for (int k = 0; k < 6; ++k) v += x[k] * w[k];
            y[e] = fmaxf((v - mean) * rstd * sLw[col] + sLb[col], 0.f);
        }
        uint32_t lo;
        uint32_t hi = pack_split(y[0], y[1], lo);
        uint32_t idx = (uint32_t)(nt * TMR + row) * 4u + (uint32_t)cp;
        actHi[idx] = hi; actLo[idx] = lo;
    }
    __syncthreads();
}

// ---------------- mid layer: k16 HMMA 3-split GEMM + LN + ReLU (+ fused out) ----
template<int HIN, int HOUT, bool LAST>
__device__ __noinline__ void mid_layer(uint8_t* sm, int lane, int mb, int nq,
    int lidx, int fidx,
    const float* __restrict__ bias, const float* __restrict__ lnw,
    const float* __restrict__ lnb, const float* __restrict__ W_out,
    const float* __restrict__ b_out, float* __restrict__ out, int rowbase)
{
    constexpr int  KT = HIN / 16;          // k16 chunks
    constexpr int  NT = HOUT / 32;         // n8-tiles per warp (warp = HOUT/4 cols)
    constexpr int  CW = HOUT * 16;         // words per chunk (both planes)
    constexpr bool DB = (HOUT == 256);     // double-buffer iff chunk is 16 KB
    constexpr int  NC4 = CW / 4 / NTHR;

    uint32_t* actHi = (uint32_t*)(sm + SM_ACT_HI);
    uint32_t* actLo = (uint32_t*)(sm + SM_ACT_LO);
    uint32_t* wbuf  = (uint32_t*)(sm + SM_WBUF);
    float* sBias  = (float*)(sm + SM_BIAS);
    float* sLw    = (float*)(sm + SM_LW);
    float* sLb    = (float*)(sm + SM_LB);
    float* sWout  = (float*)(sm + SM_WOUT);
    float* red    = (float*)(sm + SM_RED);
    float* outAcc = (float*)(sm + SM_OUTACC);
    const int tid = threadIdx.x;

    for (int i = tid; i < HOUT; i += NTHR) { sBias[i] = bias[i]; sLw[i] = lnw[i]; sLb[i] = lnb[i]; }
    if (LAST)
        for (int i = tid; i < 3 * HOUT; i += NTHR)
            sWout[i] = W_out[(i / HOUT) * 512 + (i % HOUT)];

    const uint32_t* wsrc = gW + (uint32_t)lidx * 262144u;
    auto stage = [&](int kt, int p) {
        const uint32_t* src = wsrc + (uint32_t)kt * 8192u;
        uint32_t* dst = wbuf + (DB ? p * CW : 0);
        #pragma unroll
        for (int t = 0; t < NC4; ++t) {
            int u = (tid + t * NTHR) * 4;            // word within chunk
            int hl = u / (HOUT * 8);
            int rem = u - hl * (HOUT * 8);
            cp16(dst + u, src + hl * 4096 + rem);
        }
    };

    float acc[NT][4];
    #pragma unroll
    for (int t = 0; t < NT; ++t) { acc[t][0] = acc[t][1] = acc[t][2] = acc[t][3] = 0.f; }

    const int row0 = mb * 16 + (lane >> 2);
    const int cp   = lane & 3;
    const int ntb  = nq * NT;
    const uint32_t boff = (uint32_t)((lane >> 2) * 8 + 2 * cp);

    if (DB) { stage(0, 0); cp_commit(); }

    for (int kt = 0; kt < KT; ++kt) {
        const uint32_t* B;
        if (DB) {
            cp_wait0();
            __syncthreads();
            if (kt + 1 < KT) { stage(kt + 1, (kt + 1) & 1); cp_commit(); }
            B = wbuf + (kt & 1) * CW;
        } else {
            __syncthreads();          // previous chunk's readers done
            stage(kt, 0); cp_commit(); cp_wait0();
            __syncthreads();
            B = wbuf;
        }

        uint32_t i0 = (uint32_t)((2 * kt) * TMR + row0) * 4u + cp;
        uint32_t i2 = (uint32_t)((2 * kt + 1) * TMR + row0) * 4u + cp;
        uint32_t ah0 = actHi[i0], ah1 = actHi[i0 + 32], ah2 = actHi[i2], ah3 = actHi[i2 + 32];
        uint32_t al0 = actLo[i0], al1 = actLo[i0 + 32], al2 = actLo[i2], al3 = actLo[i2 + 32];

        #pragma unroll
        for (int t = 0; t < NT; ++t) {
            const uint32_t* bp = B + (uint32_t)(ntb + t) * 64u + boff;
            uint2 bh = *(const uint2*)bp;
            uint2 bl = *(const uint2*)(bp + HOUT * 8);
            mma_k16(acc[t], ah0, ah1, ah2, ah3, bh.x, bh.y);
            mma_k16(acc[t], al0, al1, al2, al3, bh.x, bh.y);
            mma_k16(acc[t], ah0, ah1, ah2, ah3, bl.x, bl.y);
        }
    }

    // ---- epilogue ----
    float s0 = 0.f, q0 = 0.f, s1 = 0.f, q1 = 0.f;
    #pragma unroll
    for (int t = 0; t < NT; ++t) {
        float2 bv = *(const float2*)(sBias + 8 * (ntb + t) + 2 * cp);
        acc[t][0] += bv.x; acc[t][1] += bv.y; acc[t][2] += bv.x; acc[t][3] += bv.y;
        s0 += acc[t][0] + acc[t][1]; q0 += acc[t][0] * acc[t][0] + acc[t][1] * acc[t][1];
        s1 += acc[t][2] + acc[t][3]; q1 += acc[t][2] * acc[t][2] + acc[t][3] * acc[t][3];
    }
    #pragma unroll
    for (int o = 1; o <= 2; o <<= 1) {
        s0 += __shfl_xor_sync(0xffffffffu, s0, o); q0 += __shfl_xor_sync(0xffffffffu, q0, o);
        s1 += __shfl_xor_sync(0xffffffffu, s1, o); q1 += __shfl_xor_sync(0xffffffffu, q1, o);
    }
    if (cp == 0) {
        red[(nq * 32 + row0) * 2 + 0] = s0;      red[(nq * 32 + row0) * 2 + 1] = q0;
        red[(nq * 32 + row0 + 8) * 2 + 0] = s1;  red[(nq * 32 + row0 + 8) * 2 + 1] = q1;
    }
    __syncthreads();
    float S0 = 0.f, Q0 = 0.f, S1 = 0.f, Q1 = 0.f;
    #pragma unroll
    for (int g = 0; g < 4; ++g) {
        S0 += red[(g * 32 + row0) * 2 + 0];     Q0 += red[(g * 32 + row0) * 2 + 1];
        S1 += red[(g * 32 + row0 + 8) * 2 + 0]; Q1 += red[(g * 32 + row0 + 8) * 2 + 1];
    }
    const float mean0 = S0 * (1.0f / HOUT);
    const float rstd0 = rsqrtf(Q0 * (1.0f / HOUT) - mean0 * mean0 + 1e-5f);
    const float mean1 = S1 * (1.0f / HOUT);
    const float rstd1 = rsqrtf(Q1 * (1.0f / HOUT) - mean1 * mean1 + 1e-5f);

    if (!LAST) {
        #pragma unroll
        for (int t = 0; t < NT; ++t) {
            int col0 = 8 * (ntb + t) + 2 * cp;
            float2 lwv = *(const float2*)(sLw + col0);
            float2 lbv = *(const float2*)(sLb + col0);
            float y00 = fmaxf((acc[t][0] - mean0) * rstd0 * lwv.x + lbv.x, 0.f);
            float y01 = fmaxf((acc[t][1] - mean0) * rstd0 * lwv.y + lbv.y, 0.f);
            float y10 = fmaxf((acc[t][2] - mean1) * rstd1 * lwv.x + lbv.x, 0.f);
            float y11 = fmaxf((acc[t][3] - mean1) * rstd1 * lwv.y + lbv.y, 0.f);
            uint32_t lo0, lo1;
            uint32_t hi0 = pack_split(y00, y01, lo0);
            uint32_t hi1 = pack_split(y10, y11, lo1);
            uint32_t idx0 = (uint32_t)((ntb + t) * TMR + row0) * 4u + cp;
            actHi[idx0] = hi0;      actLo[idx0] = lo0;
            actHi[idx0 + 32] = hi1; actLo[idx0 + 32] = lo1;
        }
        __syncthreads();
    } else {
        float p0[3] = {0.f, 0.f, 0.f}, p1[3] = {0.f, 0.f, 0.f};
        #pragma unroll
        for (int t = 0; t < NT; ++t) {
            int col0 = 8 * (ntb + t) + 2 * cp;
            float2 lwv = *(const float2*)(sLw + col0);
            float2 lbv = *(const float2*)(sLb + col0);
            float y00 = fmaxf((acc[t][0] - mean0) * rstd0 * lwv.x + lbv.x, 0.f);
            float y01 = fmaxf((acc[t][1] - mean0) * rstd0 * lwv.y + lbv.y, 0.f);
            float y10 = fmaxf((acc[t][2] - mean1) * rstd1 * lwv.x + lbv.x, 0.f);
            float y11 = fmaxf((acc[t][3] - mean1) * rstd1 * lwv.y + lbv.y, 0.f);
            #pragma unroll
            for (int o = 0; o < 3; ++o) {
                float w0 = sWout[o * HOUT + col0], w1 = sWout[o * HOUT + col0 + 1];
                p0[o] += y00 * w0 + y01 * w1;
                p1[o] += y10 * w0 + y11 * w1;
            }
        }
        #pragma unroll
        for (int o = 0; o < 3; ++o) {
            #pragma unroll
            for (int m = 1; m <= 2; m <<= 1) {
                p0[o] += __shfl_xor_sync(0xffffffffu, p0[o], m);
                p1[o] += __shfl_xor_sync(0xffffffffu, p1[o], m);
            }
        }
        __syncthreads();   // all B-reads done before outAcc overlays wbuf
        if (cp == 0) {
            #pragma unroll
            for (int o = 0; o < 3; ++o) {
                outAcc[(nq * 32 + row0) * 3 + o] = p0[o];
                outAcc[(nq * 32 + row0 + 8) * 3 + o] = p1[o];
            }
        }
        __syncthreads();
        if (tid < 96) {
            int row = tid / 3, o = tid - row * 3;
            float v = b_out[o];
            #pragma unroll
            for (int g = 0; g < 4; ++g) v += outAcc[(g * 32 + row) * 3 + o];
            out[(size_t)(rowbase + row) * 9 + fidx * 3 + o] = v;
        }
    }
}

// ---------------- fused kernel per factor ----------------
template<int F>
__global__ void __launch_bounds__(NTHR, 2) mipnet_tc(
    const float* __restrict__ inputs,
    const float* __restrict__ W_in, const float* __restrict__ b_in,
    const float* __restrict__ bs,
    const float* __restrict__ ln_w, const float* __restrict__ ln_b,
    const float* __restrict__ W_out, const float* __restrict__ b_out,
    float* __restrict__ out)
{
    extern __shared__ uint8_t sm[];
    const int tid  = threadIdx.x;
    const int lane = tid & 31;
    const int wid  = tid >> 5;
    const int mb   = wid & 1;     // 16-row block
    const int nq   = wid >> 1;    // column quarter
    const int rowbase = blockIdx.x * TMR;

    layer0<hdim<F>(0)>(sm, inputs, W_in, b_in, ln_w, ln_b, rowbase);
    mid_layer<hdim<F>(0), hdim<F>(1), false>(sm, lane, mb, nq, 0, F, bs,
        ln_w + 512,  ln_b + 512,  W_out, b_out, out, rowbase);
    mid_layer<hdim<F>(1), hdim<F>(2), false>(sm, lane, mb, nq, 1, F, bs + 512,
        ln_w + 1024, ln_b + 1024, W_out, b_out, out, rowbase);
    mid_layer<hdim<F>(2), hdim<F>(3), false>(sm, lane, mb, nq, 2, F, bs + 1024,
        ln_w + 1536, ln_b + 1536, W_out, b_out, out, rowbase);
    mid_layer<hdim<F>(3), hdim<F>(4), false>(sm, lane, mb, nq, 3, F, bs + 1536,
        ln_w + 2048, ln_b + 2048, W_out, b_out, out, rowbase);
    mid_layer<hdim<F>(4), hdim<F>(5), false>(sm, lane, mb, nq, 4, F, bs + 2048,
        ln_w + 2560, ln_b + 2560, W_out, b_out, out, rowbase);
    mid_layer<hdim<F>(5), hdim<F>(6), true >(sm, lane, mb, nq, 5, F, bs + 2560,
        ln_w + 3072, ln_b + 3072, W_out, b_out, out, rowbase);
}

extern "C" void kernel_launch(void* const* d_in, const int* in_sizes, int n_in,
                              void* d_out, int out_size) {
    const float* inputs = (const float*)d_in[0];
    const float* W_in   = (const float*)d_in[1];
    const float* b_in   = (const float*)d_in[2];
    const float* Ws     = (const float*)d_in[3];
    const float* bs     = (const float*)d_in[4];
    const float* ln_w   = (const float*)d_in[5];
    const float* ln_b   = (const float*)d_in[6];
    const float* W_out  = (const float*)d_in[7];
    const float* b_out  = (const float*)d_in[8];
    float* out = (float*)d_out;

    const int Nrows = in_sizes[0] / 6;
    const int tiles = Nrows / TMR;      // 4096

    cudaFuncSetAttribute(mipnet_tc<0>, cudaFuncAttributeMaxDynamicSharedMemorySize, SM_TOTAL);
    cudaFuncSetAttribute(mipnet_tc<1>, cudaFuncAttributeMaxDynamicSharedMemorySize, SM_TOTAL);
    cudaFuncSetAttribute(mipnet_tc<2>, cudaFuncAttributeMaxDynamicSharedMemorySize, SM_TOTAL);

    split_weights<<<3072, 256>>>(Ws);

    mipnet_tc<0><<<tiles, NTHR, SM_TOTAL>>>(inputs, W_in, b_in, bs, ln_w, ln_b, W_out, b_out, out);
    mipnet_tc<1><<<tiles, NTHR, SM_TOTAL>>>(inputs, W_in, b_in, bs, ln_w, ln_b, W_out, b_out, out);
    mipnet_tc<2><<<tiles, NTHR, SM_TOTAL>>>(inputs, W_in, b_in, bs, ln_w, ln_b, W_out, b_out, out);
}

// round 13
// speedup vs baseline: 1.4682x; 1.0422x over previous
#include <cuda_runtime.h>
#include <cuda_bf16.h>
#include <cstdint>

#define NTHR 256
#define TMR  32

// Weight blob (k16 layout): per layer 32 k16-chunks x [hl][n][pos].
// word(l, kt, hl, n, pos) at (l*32+kt)*8192 + hl*4096 + n*8 + pos,
// pos = 2*(kpl&3) + (kpl>>2) for k-pair kpl (0..7): B-fragment pair (kpl, kpl+4)
// is one contiguous 8B load: uint2 at  nt*64 + (lane>>2)*8 + 2*(lane&3).
__device__ __align__(16) uint32_t gW[6u * 262144u];   // 6 MB

// ---- smem byte offsets ----
#define SM_ACT_HI 0         // 8192 words (32 rows x 512 cols bf16-pairs)
#define SM_ACT_LO 32768     // 8192 words
#define SM_WBUF   65536     // 32 KB = 2 x 16KB plane buffers
#define SM_BIAS   98304     // 512 f
#define SM_LW     100352    // 512 f
#define SM_LB     102400    // 512 f
#define SM_WOUT   104448    // 3*512 f
#define SM_RED    110592    // 8*32*2 f = 2048 B
#define SM_TOTAL  112640
// overlays inside WBUF (only when weight buffer is dead):
#define SM_XIN    SM_WBUF   // layer0 input staging
#define SM_OUTACC SM_WBUF   // LAST epilogue partials (8*32*3 f)

__device__ __forceinline__ void cp16(void* dst, const void* src) {
    unsigned s = (unsigned)__cvta_generic_to_shared(dst);
    asm volatile("cp.async.cg.shared.global [%0], [%1], 16;" :: "r"(s), "l"(src));
}
__device__ __forceinline__ void cp_commit() { asm volatile("cp.async.commit_group;"); }
__device__ __forceinline__ void cp_wait0()  { asm volatile("cp.async.wait_group 0;"); }

__device__ __forceinline__ void mma_k16(float* d,
                                        uint32_t a0, uint32_t a1, uint32_t a2, uint32_t a3,
                                        uint32_t b0, uint32_t b1) {
    asm volatile("mma.sync.aligned.m16n8k16.row.col.f32.bf16.bf16.f32 "
        "{%0,%1,%2,%3}, {%4,%5,%6,%7}, {%8,%9}, {%0,%1,%2,%3};"
        : "+f"(d[0]), "+f"(d[1]), "+f"(d[2]), "+f"(d[3])
        : "r"(a0), "r"(a1), "r"(a2), "r"(a3), "r"(b0), "r"(b1));
}

__device__ __forceinline__ uint32_t pack_split(float a, float b, uint32_t& lo) {
    __nv_bfloat16 ha = __float2bfloat16(a), hb = __float2bfloat16(b);
    __nv_bfloat16 la = __float2bfloat16(a - __bfloat162float(ha));
    __nv_bfloat16 lb = __float2bfloat16(b - __bfloat162float(hb));
    lo = (uint32_t)__bfloat16_as_ushort(la) | ((uint32_t)__bfloat16_as_ushort(lb) << 16);
    return (uint32_t)__bfloat16_as_ushort(ha) | ((uint32_t)__bfloat16_as_ushort(hb) << 16);
}

template<int F>
__host__ __device__ constexpr int hdim(int l) {
    return (F == 0) ? 256 : ((F == 2) ? 512 : ((l % 2 == 0) ? 512 : 256));
}

// ---------------- prep: split fp32 weights into hi/lo bf16 blob (k16 layout) ----
__global__ void split_weights(const float* __restrict__ Ws) {
    int id = blockIdx.x * 256 + threadIdx.x;        // 6*512*256 k-pairs
    int l  = id / (512 * 256);
    int r  = id - l * (512 * 256);
    int n  = r >> 8;
    int kp = r & 255;
    const float* W = Ws + ((size_t)l * 512 + n) * 512;
    float w0 = W[2 * kp], w1 = W[2 * kp + 1];
    __nv_bfloat16 h0 = __float2bfloat16(w0), h1 = __float2bfloat16(w1);
    __nv_bfloat16 l0 = __float2bfloat16(w0 - __bfloat162float(h0));
    __nv_bfloat16 l1 = __float2bfloat16(w1 - __bfloat162float(h1));
    int kt = kp >> 3, kpl = kp & 7;
    int pos = 2 * (kpl & 3) + (kpl >> 2);
    uint32_t base = (uint32_t)((l * 32 + kt) * 2) * 4096u + (uint32_t)(n * 8 + pos);
    gW[base]        = (uint32_t)__bfloat16_as_ushort(h0) | ((uint32_t)__bfloat16_as_ushort(h1) << 16);
    gW[base + 4096] = (uint32_t)__bfloat16_as_ushort(l0) | ((uint32_t)__bfloat16_as_ushort(l1) << 16);
}

// ---------------- layer 0 (K = 6) ----------------
template<int HOUT>
__device__ __noinline__ void layer0(uint8_t* sm,
    const float* __restrict__ inputs, const float* __restrict__ W_in,
    const float* __restrict__ b_in, const float* __restrict__ lnw,
    const float* __restrict__ lnb, int rowbase)
{
    uint32_t* actHi = (uint32_t*)(sm + SM_ACT_HI);
    uint32_t* actLo = (uint32_t*)(sm + SM_ACT_LO);
    float* sW    = (float*)(sm + SM_WBUF + 4096);   // after xin, inside dead wbuf
    float* sBias = (float*)(sm + SM_BIAS);
    float* sLw   = (float*)(sm + SM_LW);
    float* sLb   = (float*)(sm + SM_LB);
    float* xin   = (float*)(sm + SM_XIN);
    const int tid = threadIdx.x;

    for (int i = tid; i < HOUT * 6; i += NTHR) sW[i] = W_in[i];
    for (int i = tid; i < HOUT; i += NTHR) { sBias[i] = b_in[i]; sLw[i] = lnw[i]; sLb[i] = lnb[i]; }
    for (int i = tid; i < TMR * 6; i += NTHR) xin[i] = inputs[rowbase * 6 + i];
    __syncthreads();

    const int row = tid >> 3, sub = (tid >> 2) & 1, cp = tid & 3;
    float x[6];
    #pragma unroll
    for (int k = 0; k < 6; ++k) x[k] = xin[row * 6 + k];

    float s = 0.f, q = 0.f;
    for (int nt = sub; nt < HOUT / 8; nt += 2) {
        #pragma unroll
        for (int e = 0; e < 2; ++e) {
            int col = 8 * nt + 2 * cp + e;
            const float* w = sW + col * 6;
            float v = sBias[col];
            #pragma unroll
            for (int k = 0; k < 6; ++k) v += x[k] * w[k];
            s += v; q += v * v;
        }
    }
    #pragma unroll
    for (int o = 1; o <= 4; o <<= 1) {
        s += __shfl_xor_sync(0xffffffffu, s, o);
        q += __shfl_xor_sync(0xffffffffu, q, o);
    }
    const float mean = s * (1.0f / HOUT);
    const float rstd = rsqrtf(q * (1.0f / HOUT) - mean * mean + 1e-5f);

    for (int nt = sub; nt < HOUT / 8; nt += 2) {
        float y[2];
        #pragma unroll
        for (int e = 0; e < 2; ++e) {
            int col = 8 * nt + 2 * cp + e;
            const float* w = sW + col * 6;
            float v = sBias[col];
            #pragma unroll
            for (int k = 0; k < 6; ++k) v += x[k] * w[k];
            y[e] = fmaxf((v - mean) * rstd * sLw[col] + sLb[col], 0.f);
        }
        uint32_t lo;
        uint32_t hi = pack_split(y[0], y[1], lo);
        uint32_t idx = (uint32_t)(nt * TMR + row) * 4u + (uint32_t)cp;
        actHi[idx] = hi; actLo[idx] = lo;
    }
    __syncthreads();
}

// ---- mid layer: k16 HMMA 3-split GEMM, plane-DB, warp = 32 rows x HOUT/8 cols ----
template<int HIN, int HOUT, bool LAST>
__device__ __noinline__ void mid_layer(uint8_t* sm, int lane, int w,
    int lidx, int fidx,
    const float* __restrict__ bias, const float* __restrict__ lnw,
    const float* __restrict__ lnb, const float* __restrict__ W_out,
    const float* __restrict__ b_out, float* __restrict__ out, int rowbase)
{
    constexpr int KT  = HIN / 16;          // k16 chunks
    constexpr int NU  = 2 * KT;            // plane units
    constexpr int NT  = HOUT / 64;         // n8-tiles per warp (warp = HOUT/8 cols)
    constexpr int PW  = HOUT * 8;          // words per plane
    constexpr int NC4 = PW / 4 / NTHR;     // uint4 copies per thread per plane

    uint32_t* actHi = (uint32_t*)(sm + SM_ACT_HI);
    uint32_t* actLo = (uint32_t*)(sm + SM_ACT_LO);
    uint32_t* wbuf  = (uint32_t*)(sm + SM_WBUF);
    float* sBias  = (float*)(sm + SM_BIAS);
    float* sLw    = (float*)(sm + SM_LW);
    float* sLb    = (float*)(sm + SM_LB);
    float* sWout  = (float*)(sm + SM_WOUT);
    float* red    = (float*)(sm + SM_RED);
    float* outAcc = (float*)(sm + SM_OUTACC);
    const int tid = threadIdx.x;

    for (int i = tid; i < HOUT; i += NTHR) { sBias[i] = bias[i]; sLw[i] = lnw[i]; sLb[i] = lnb[i]; }
    if (LAST)
        for (int i = tid; i < 3 * HOUT; i += NTHR)
            sWout[i] = W_out[(i / HOUT) * 512 + (i % HOUT)];

    const uint32_t* wsrc = gW + (uint32_t)lidx * 262144u;
    auto stage = [&](int u) {
        const uint32_t* src = wsrc + (uint32_t)(u >> 1) * 8192u + (uint32_t)(u & 1) * 4096u;
        uint32_t* dst = wbuf + (u & 1) * 4096;
        #pragma unroll
        for (int t = 0; t < NC4; ++t) {
            int v = (tid + t * NTHR) * 4;
            cp16(dst + v, src + v);
        }
    };

    float acc[2][NT][4];
    #pragma unroll
    for (int mb = 0; mb < 2; ++mb)
        #pragma unroll
        for (int t = 0; t < NT; ++t)
            acc[mb][t][0] = acc[mb][t][1] = acc[mb][t][2] = acc[mb][t][3] = 0.f;

    const int r  = lane >> 2;
    const int cp = lane & 3;
    const int ntb = w * NT;
    const uint32_t boff = (uint32_t)(r * 8 + 2 * cp);
    uint32_t ah[2][4];   // hi A-frags persist from hi-unit to lo-unit

    stage(0); cp_commit();
    for (int u = 0; u < NU; ++u) {
        cp_wait0();
        __syncthreads();
        if (u + 1 < NU) { stage(u + 1); cp_commit(); }

        const uint32_t* B = wbuf + (u & 1) * 4096;
        const int kt = u >> 1;

        if ((u & 1) == 0) {
            uint32_t al[2][4];
            #pragma unroll
            for (int mb = 0; mb < 2; ++mb) {
                uint32_t i0 = (uint32_t)((2 * kt) * TMR + mb * 16 + r) * 4u + cp;
                uint32_t i2 = (uint32_t)((2 * kt + 1) * TMR + mb * 16 + r) * 4u + cp;
                ah[mb][0] = actHi[i0]; ah[mb][1] = actHi[i0 + 32];
                ah[mb][2] = actHi[i2]; ah[mb][3] = actHi[i2 + 32];
                al[mb][0] = actLo[i0]; al[mb][1] = actLo[i0 + 32];
                al[mb][2] = actLo[i2]; al[mb][3] = actLo[i2 + 32];
            }
            #pragma unroll
            for (int t = 0; t < NT; ++t) {
                uint2 bh = *(const uint2*)(B + (uint32_t)(ntb + t) * 64u + boff);
                #pragma unroll
                for (int mb = 0; mb < 2; ++mb) {
                    mma_k16(acc[mb][t], ah[mb][0], ah[mb][1], ah[mb][2], ah[mb][3], bh.x, bh.y);
                    mma_k16(acc[mb][t], al[mb][0], al[mb][1], al[mb][2], al[mb][3], bh.x, bh.y);
                }
            }
        } else {
            #pragma unroll
            for (int t = 0; t < NT; ++t) {
                uint2 bl = *(const uint2*)(B + (uint32_t)(ntb + t) * 64u + boff);
                #pragma unroll
                for (int mb = 0; mb < 2; ++mb)
                    mma_k16(acc[mb][t], ah[mb][0], ah[mb][1], ah[mb][2], ah[mb][3], bl.x, bl.y);
            }
        }
    }

    // ---- epilogue: 4 row-slots per thread: rows mb*16 + r + 8*h ----
    float sv[2][2], qv[2][2];
    #pragma unroll
    for (int mb = 0; mb < 2; ++mb) { sv[mb][0] = sv[mb][1] = qv[mb][0] = qv[mb][1] = 0.f; }
    #pragma unroll
    for (int mb = 0; mb < 2; ++mb)
        #pragma unroll
        for (int t = 0; t < NT; ++t) {
            float2 bv = *(const float2*)(sBias + 8 * (ntb + t) + 2 * cp);
            acc[mb][t][0] += bv.x; acc[mb][t][1] += bv.y;
            acc[mb][t][2] += bv.x; acc[mb][t][3] += bv.y;
            sv[mb][0] += acc[mb][t][0] + acc[mb][t][1];
            qv[mb][0] += acc[mb][t][0] * acc[mb][t][0] + acc[mb][t][1] * acc[mb][t][1];
            sv[mb][1] += acc[mb][t][2] + acc[mb][t][3];
            qv[mb][1] += acc[mb][t][2] * acc[mb][t][2] + acc[mb][t][3] * acc[mb][t][3];
        }
    #pragma unroll
    for (int o = 1; o <= 2; o <<= 1)
        #pragma unroll
        for (int mb = 0; mb < 2; ++mb)
            #pragma unroll
            for (int h = 0; h < 2; ++h) {
                sv[mb][h] += __shfl_xor_sync(0xffffffffu, sv[mb][h], o);
                qv[mb][h] += __shfl_xor_sync(0xffffffffu, qv[mb][h], o);
            }
    if (cp == 0) {
        #pragma unroll
        for (int mb = 0; mb < 2; ++mb)
            #pragma unroll
            for (int h = 0; h < 2; ++h) {
                int row = mb * 16 + r + 8 * h;
                red[(w * 32 + row) * 2 + 0] = sv[mb][h];
                red[(w * 32 + row) * 2 + 1] = qv[mb][h];
            }
    }
    __syncthreads();

    float mean_[2][2], rstd_[2][2];
    #pragma unroll
    for (int mb = 0; mb < 2; ++mb)
        #pragma unroll
        for (int h = 0; h < 2; ++h) {
            int row = mb * 16 + r + 8 * h;
            float S = 0.f, Q = 0.f;
            #pragma unroll
            for (int g = 0; g < 8; ++g) {
                float2 e = *(const float2*)(red + (g * 32 + row) * 2);
                S += e.x; Q += e.y;
            }
            float m = S * (1.0f / HOUT);
            mean_[mb][h] = m;
            rstd_[mb][h] = rsqrtf(Q * (1.0f / HOUT) - m * m + 1e-5f);
        }

    if (!LAST) {
        #pragma unroll
        for (int mb = 0; mb < 2; ++mb)
            #pragma unroll
            for (int t = 0; t < NT; ++t) {
                int col0 = 8 * (ntb + t) + 2 * cp;
                float2 lwv = *(const float2*)(sLw + col0);
                float2 lbv = *(const float2*)(sLb + col0);
                float y00 = fmaxf((acc[mb][t][0] - mean_[mb][0]) * rstd_[mb][0] * lwv.x + lbv.x, 0.f);
                float y01 = fmaxf((acc[mb][t][1] - mean_[mb][0]) * rstd_[mb][0] * lwv.y + lbv.y, 0.f);
                float y10 = fmaxf((acc[mb][t][2] - mean_[mb][1]) * rstd_[mb][1] * lwv.x + lbv.x, 0.f);
                float y11 = fmaxf((acc[mb][t][3] - mean_[mb][1]) * rstd_[mb][1] * lwv.y + lbv.y, 0.f);
                uint32_t lo0, lo1;
                uint32_t hi0 = pack_split(y00, y01, lo0);
                uint32_t hi1 = pack_split(y10, y11, lo1);
                uint32_t idx0 = (uint32_t)((ntb + t) * TMR + mb * 16 + r) * 4u + cp;
                actHi[idx0] = hi0;      actLo[idx0] = lo0;
                actHi[idx0 + 32] = hi1; actLo[idx0 + 32] = lo1;
            }
        __syncthreads();
    } else {
        float p[2][2][3];
        #pragma unroll
        for (int mb = 0; mb < 2; ++mb)
            #pragma unroll
            for (int h = 0; h < 2; ++h)
                p[mb][h][0] = p[mb][h][1] = p[mb][h][2] = 0.f;
        #pragma unroll
        for (int mb = 0; mb < 2; ++mb)
            #pragma unroll
            for (int t = 0; t < NT; ++t) {
                int col0 = 8 * (ntb + t) + 2 * cp;
                float2 lwv = *(const float2*)(sLw + col0);
                float2 lbv = *(const float2*)(sLb + col0);
                float y00 = fmaxf((acc[mb][t][0] - mean_[mb][0]) * rstd_[mb][0] * lwv.x + lbv.x, 0.f);
                float y01 = fmaxf((acc[mb][t][1] - mean_[mb][0]) * rstd_[mb][0] * lwv.y + lbv.y, 0.f);
                float y10 = fmaxf((acc[mb][t][2] - mean_[mb][1]) * rstd_[mb][1] * lwv.x + lbv.x, 0.f);
                float y11 = fmaxf((acc[mb][t][3] - mean_[mb][1]) * rstd_[mb][1] * lwv.y + lbv.y, 0.f);
                #pragma unroll
                for (int o = 0; o < 3; ++o) {
                    float w0 = sWout[o * HOUT + col0], w1 = sWout[o * HOUT + col0 + 1];
                    p[mb][0][o] += y00 * w0 + y01 * w1;
                    p[mb][1][o] += y10 * w0 + y11 * w1;
                }
            }
        #pragma unroll
        for (int o = 0; o < 3; ++o)
            #pragma unroll
            for (int mb = 0; mb < 2; ++mb)
                #pragma unroll
                for (int h = 0; h < 2; ++h) {
                    p[mb][h][o] += __shfl_xor_sync(0xffffffffu, p[mb][h][o], 1);
                    p[mb][h][o] += __shfl_xor_sync(0xffffffffu, p[mb][h][o], 2);
                }
        if (cp == 0) {
            #pragma unroll
            for (int mb = 0; mb < 2; ++mb)
                #pragma unroll
                for (int h = 0; h < 2; ++h) {
                    int row = mb * 16 + r + 8 * h;
                    #pragma unroll
                    for (int o = 0; o < 3; ++o)
                        outAcc[(w * 32 + row) * 3 + o] = p[mb][h][o];
                }
        }
        __syncthreads();
        if (tid < 96) {
            int row = tid / 3, o = tid - row * 3;
            float v = b_out[o];
            #pragma unroll
            for (int g = 0; g < 8; ++g) v += outAcc[(g * 32 + row) * 3 + o];
            out[(size_t)(rowbase + row) * 9 + fidx * 3 + o] = v;
        }
    }
}

// ---------------- fused kernel per factor ----------------
template<int F>
__global__ void __launch_bounds__(NTHR, 2) mipnet_tc(
    const float* __restrict__ inputs,
    const float* __restrict__ W_in, const float* __restrict__ b_in,
    const float* __restrict__ bs,
    const float* __restrict__ ln_w, const float* __restrict__ ln_b,
    const float* __restrict__ W_out, const float* __restrict__ b_out,
    float* __restrict__ out)
{
    extern __shared__ uint8_t sm[];
    const int tid  = threadIdx.x;
    const int lane = tid & 31;
    const int w    = tid >> 5;    // warp = column eighth, all 32 rows
    const int rowbase = blockIdx.x * TMR;

    layer0<hdim<F>(0)>(sm, inputs, W_in, b_in, ln_w, ln_b, rowbase);
    mid_layer<hdim<F>(0), hdim<F>(1), false>(sm, lane, w, 0, F, bs,
        ln_w + 512,  ln_b + 512,  W_out, b_out, out, rowbase);
    mid_layer<hdim<F>(1), hdim<F>(2), false>(sm, lane, w, 1, F, bs + 512,
        ln_w + 1024, ln_b + 1024, W_out, b_out, out, rowbase);
    mid_layer<hdim<F>(2), hdim<F>(3), false>(sm, lane, w, 2, F, bs + 1024,
        ln_w + 1536, ln_b + 1536, W_out, b_out, out, rowbase);
    mid_layer<hdim<F>(3), hdim<F>(4), false>(sm, lane, w, 3, F, bs + 1536,
        ln_w + 2048, ln_b + 2048, W_out, b_out, out, rowbase);
    mid_layer<hdim<F>(4), hdim<F>(5), false>(sm, lane, w, 4, F, bs + 2048,
        ln_w + 2560, ln_b + 2560, W_out, b_out, out, rowbase);
    mid_layer<hdim<F>(5), hdim<F>(6), true >(sm, lane, w, 5, F, bs + 2560,
        ln_w + 3072, ln_b + 3072, W_out, b_out, out, rowbase);
}

extern "C" void kernel_launch(void* const* d_in, const int* in_sizes, int n_in,
                              void* d_out, int out_size) {
    const float* inputs = (const float*)d_in[0];
    const float* W_in   = (const float*)d_in[1];
    const float* b_in   = (const float*)d_in[2];
    const float* Ws     = (const float*)d_in[3];
    const float* bs     = (const float*)d_in[4];
    const float* ln_w   = (const float*)d_in[5];
    const float* ln_b   = (const float*)d_in[6];
    const float* W_out  = (const float*)d_in[7];
    const float* b_out  = (const float*)d_in[8];
    float* out = (float*)d_out;

    const int Nrows = in_sizes[0] / 6;
    const int tiles = Nrows / TMR;      // 4096

    cudaFuncSetAttribute(mipnet_tc<0>, cudaFuncAttributeMaxDynamicSharedMemorySize, SM_TOTAL);
    cudaFuncSetAttribute(mipnet_tc<1>, cudaFuncAttributeMaxDynamicSharedMemorySize, SM_TOTAL);
    cudaFuncSetAttribute(mipnet_tc<2>, cudaFuncAttributeMaxDynamicSharedMemorySize, SM_TOTAL);

    split_weights<<<3072, 256>>>(Ws);

    mipnet_tc<0><<<tiles, NTHR, SM_TOTAL>>>(inputs, W_in, b_in, bs, ln_w, ln_b, W_out, b_out, out);
    mipnet_tc<1><<<tiles, NTHR, SM_TOTAL>>>(inputs, W_in, b_in, bs, ln_w, ln_b, W_out, b_out, out);
    mipnet_tc<2><<<tiles, NTHR, SM_TOTAL>>>(inputs, W_in, b_in, bs, ln_w, ln_b, W_out, b_out, out);
}